// round 2
// baseline (speedup 1.0000x reference)
#include <cuda_runtime.h>
#include <cstdint>
#include <math_constants.h>

// Problem shape (fixed for this dataset; V/B derived at runtime from in_sizes)
#define E_DIM 128
#define THREADS 256
#define RB 4                       // rows (batch) per block in GEMM2
#define QPT 3                      // float4 quads per thread per iter
#define CPT (4*QPT)                // 12 columns per thread per iter
#define COLS_PER_ITER (THREADS*CPT)// 3072
#define VPAD_MAX 50432
#define BMAX 1024

// Scratch (static device globals: allocation-free per harness rules)
__device__ float g_W[(size_t)E_DIM * VPAD_MAX];   // repacked embed2vocab, rows padded to 16B alignment
__device__ float g_emb[(size_t)BMAX * E_DIM];     // xsembeds = xs @ EMBEDM

// ---------------- packed f32x2 helpers (PTX-only on sm_103a) ----------------
__device__ __forceinline__ void fma2(unsigned long long& d, unsigned long long a, unsigned long long b){
  asm("fma.rn.f32x2 %0, %1, %2, %0;" : "+l"(d) : "l"(a), "l"(b));
}
__device__ __forceinline__ unsigned long long pack2(float x){
  unsigned long long r; asm("mov.b64 %0, {%1, %1};" : "=l"(r) : "f"(x)); return r;
}
__device__ __forceinline__ void unpack2(float& lo, float& hi, unsigned long long v){
  asm("mov.b64 {%0, %1}, %2;" : "=f"(lo), "=f"(hi) : "l"(v));
}
__device__ __forceinline__ float f4c(const float4 v, int ee){
  return ee==0 ? v.x : (ee==1 ? v.y : (ee==2 ? v.z : v.w));
}
// online (max, sumexp) update
__device__ __forceinline__ void onl(float& m, float& s, float x){
  if (x > m){ s = s*__expf(m - x) + 1.f; m = x; }
  else      { s += __expf(x - m); }
}

// ---------------- K0: repack embed2vocab [E,V] into padded g_W [E,vpad] ----------------
__global__ void repack_kernel(const float* __restrict__ W, int V, int vpad){
  const int e = blockIdx.x;
  const float* src = W + (size_t)e * V;
  float* dst = g_W + (size_t)e * vpad;
  for (int v = threadIdx.x + blockIdx.y * blockDim.x; v < V; v += blockDim.x * gridDim.y)
    dst[v] = src[v];
}

// ---------------- K1: sparse scan + gather: xsembeds = xs @ EMBEDM ----------------
__global__ void gather_kernel(const float* __restrict__ xs, const float* __restrict__ EM, int V){
  __shared__ int   s_cnt;
  __shared__ int   s_v[1024];
  __shared__ float s_w[1024];
  const int b = blockIdx.x;
  const int tid = threadIdx.x;
  if (tid == 0) s_cnt = 0;
  __syncthreads();

  const float* row = xs + (size_t)b * V;
  // align to 16B for float4 scanning
  int a0 = (int)(((16u - ((unsigned)(uintptr_t)row & 15u)) & 15u) >> 2);
  if (a0 > V) a0 = V;
  const int n4 = (V - a0) >> 2;
  const float4* row4 = (const float4*)(row + a0);

  for (int j = tid; j < n4; j += THREADS){
    float4 x = row4[j];
    const int base = a0 + 4*j;
    if (x.x != 0.f){ int p = atomicAdd(&s_cnt,1); if (p<1024){ s_v[p]=base;   s_w[p]=x.x; } }
    if (x.y != 0.f){ int p = atomicAdd(&s_cnt,1); if (p<1024){ s_v[p]=base+1; s_w[p]=x.y; } }
    if (x.z != 0.f){ int p = atomicAdd(&s_cnt,1); if (p<1024){ s_v[p]=base+2; s_w[p]=x.z; } }
    if (x.w != 0.f){ int p = atomicAdd(&s_cnt,1); if (p<1024){ s_v[p]=base+3; s_w[p]=x.w; } }
  }
  for (int i = tid; i < a0; i += THREADS){
    float x = row[i];
    if (x != 0.f){ int p = atomicAdd(&s_cnt,1); if (p<1024){ s_v[p]=i; s_w[p]=x; } }
  }
  for (int i = a0 + 4*n4 + tid; i < V; i += THREADS){
    float x = row[i];
    if (x != 0.f){ int p = atomicAdd(&s_cnt,1); if (p<1024){ s_v[p]=i; s_w[p]=x; } }
  }
  __syncthreads();

  int cnt = s_cnt; if (cnt > 1024) cnt = 1024;
  if (tid < E_DIM){
    float acc = 0.f;
    for (int k = 0; k < cnt; k++)
      acc = fmaf(s_w[k], EM[(size_t)s_v[k]*E_DIM + tid], acc);
    g_emb[(size_t)b*E_DIM + tid] = acc;
  }
}

// ---------------- K2: fused [B,E]@[E,V] + log_softmax ----------------
// One block owns RB=4 full rows: pass1 computes logits (f32x2 FMAs), writes them,
// tracks online (max,sumexp); block-reduce; pass2 rereads own rows (L2-hot) and
// subtracts lse in-place with float4.
__global__ void __launch_bounds__(THREADS)
gemm_lsm_kernel(float* __restrict__ out, int V, int vpad){
  __shared__ float4 s_emb4[RB][E_DIM/4];
  __shared__ float  s_rm[RB][THREADS];
  __shared__ float  s_rs[RB][THREADS];
  __shared__ float  s_lse[RB];

  const int tid = threadIdx.x;
  const int r0  = blockIdx.x * RB;

  if (tid < RB*E_DIM/4)
    ((float4*)s_emb4)[tid] = ((const float4*)(g_emb + (size_t)r0*E_DIM))[tid];
  __syncthreads();

  float m[RB], s[RB];
#pragma unroll
  for (int r = 0; r < RB; r++){ m[r] = -CUDART_INF_F; s[r] = 0.f; }

  const int full_iters = V / COLS_PER_ITER;
  for (int it = 0; it < full_iters; it++){
    const int cbase = it*COLS_PER_ITER + 4*tid;
    unsigned long long acc[RB][2*QPT];
#pragma unroll
    for (int r = 0; r < RB; r++)
#pragma unroll
      for (int p = 0; p < 2*QPT; p++) acc[r][p] = 0ull;

    const float* Wb = g_W + cbase;
    for (int e4 = 0; e4 < E_DIM/4; e4++){
      float4 xe[RB];
#pragma unroll
      for (int r = 0; r < RB; r++) xe[r] = s_emb4[r][e4];
      const float* We = Wb + (size_t)(4*e4) * vpad;
#pragma unroll
      for (int ee = 0; ee < 4; ee++){
        // 16B-aligned: g_W base + cbase (mult of 4 floats) + e*vpad (vpad mult of 32)
        ulonglong2 w0 = *(const ulonglong2*)(We);
        ulonglong2 w1 = *(const ulonglong2*)(We + 1024);
        ulonglong2 w2 = *(const ulonglong2*)(We + 2048);
#pragma unroll
        for (int r = 0; r < RB; r++){
          unsigned long long x2 = pack2(f4c(xe[r], ee));
          fma2(acc[r][0], x2, w0.x);
          fma2(acc[r][1], x2, w0.y);
          fma2(acc[r][2], x2, w1.x);
          fma2(acc[r][3], x2, w1.y);
          fma2(acc[r][4], x2, w2.x);
          fma2(acc[r][5], x2, w2.y);
        }
        We += vpad;
      }
    }
    // stats + scalar stores (rows misaligned mod 16B since V is odd)
#pragma unroll
    for (int r = 0; r < RB; r++){
      float* orow = out + (size_t)(r0+r)*V + cbase;
#pragma unroll
      for (int p = 0; p < 2*QPT; p++){
        float lo, hi; unpack2(lo, hi, acc[r][p]);
        onl(m[r], s[r], lo); onl(m[r], s[r], hi);
        const int off = (p>>1)*1024 + (p&1)*2;
        orow[off]   = lo;
        orow[off+1] = hi;
      }
    }
  }

  // tail columns [full_iters*3072, V)
  for (int cb = full_iters*COLS_PER_ITER; cb < V; cb += THREADS){
    const int c = cb + tid;
    if (c < V){
      float ta[RB];
#pragma unroll
      for (int r = 0; r < RB; r++) ta[r] = 0.f;
      const float* Wc = g_W + c;
      for (int e4 = 0; e4 < E_DIM/4; e4++){
        float4 xe[RB];
#pragma unroll
        for (int r = 0; r < RB; r++) xe[r] = s_emb4[r][e4];
#pragma unroll
        for (int ee = 0; ee < 4; ee++){
          const float w = Wc[(size_t)(4*e4+ee)*vpad];
#pragma unroll
          for (int r = 0; r < RB; r++)
            ta[r] = fmaf(f4c(xe[r], ee), w, ta[r]);
        }
      }
#pragma unroll
      for (int r = 0; r < RB; r++){
        onl(m[r], s[r], ta[r]);
        out[(size_t)(r0+r)*V + c] = ta[r];
      }
    }
  }

  // block reduce (max, sumexp) per row
#pragma unroll
  for (int r = 0; r < RB; r++){ s_rm[r][tid] = m[r]; s_rs[r][tid] = s[r]; }
  __syncthreads();
  for (int st = THREADS/2; st > 0; st >>= 1){
    if (tid < st){
#pragma unroll
      for (int r = 0; r < RB; r++){
        const float m1 = s_rm[r][tid],     s1 = s_rs[r][tid];
        const float m2 = s_rm[r][tid+st],  s2 = s_rs[r][tid+st];
        const float mm = fmaxf(m1, m2);
        s_rm[r][tid] = mm;
        s_rs[r][tid] = s1*__expf(m1-mm) + s2*__expf(m2-mm);
      }
    }
    __syncthreads();
  }
  if (tid < RB) s_lse[tid] = s_rm[tid][0] + logf(s_rs[tid][0]);
  __syncthreads();

  // pass 2: subtract lse in-place; 4-row span (4*V floats) is 16B aligned & exactly V float4s
  const float l0 = s_lse[0], l1 = s_lse[1], l2 = s_lse[2], l3 = s_lse[3];
  float4* ob = (float4*)(out + (size_t)r0 * V);
  const int V1 = V, V2 = 2*V, V3 = 3*V;
  for (int j = tid; j < V; j += THREADS){
    float4 x = ob[j];
    const int i = 4*j;
    x.x -= (i   >= V2) ? ((i   >= V3) ? l3 : l2) : ((i   >= V1) ? l1 : l0);
    x.y -= (i+1 >= V2) ? ((i+1 >= V3) ? l3 : l2) : ((i+1 >= V1) ? l1 : l0);
    x.z -= (i+2 >= V2) ? ((i+2 >= V3) ? l3 : l2) : ((i+2 >= V1) ? l1 : l0);
    x.w -= (i+3 >= V2) ? ((i+3 >= V3) ? l3 : l2) : ((i+3 >= V1) ? l1 : l0);
    ob[j] = x;
  }
}

extern "C" void kernel_launch(void* const* d_in, const int* in_sizes, int n_in,
                              void* d_out, int out_size){
  const float* xs = (const float*)d_in[0];
  // d_in[1] = metric (unused by forward)
  const float* EM = (const float*)d_in[2];
  const float* W  = (const float*)d_in[3];
  float* out = (float*)d_out;

  const int E = E_DIM;                 // in_sizes[1] == E*E == 16384
  const int V = in_sizes[3] / E;       // 50257
  const int B = in_sizes[0] / V;       // 1024
  int vpad = (V + 31) & ~31;
  if (vpad > VPAD_MAX) vpad = VPAD_MAX;

  dim3 rg(E, 8);
  repack_kernel<<<rg, 256>>>(W, V, vpad);
  gather_kernel<<<B, THREADS>>>(xs, EM, V);
  gemm_lsm_kernel<<<B/RB, THREADS>>>(out, V, vpad);
}

// round 4
// speedup vs baseline: 1.9474x; 1.9474x over previous
#include <cuda_runtime.h>
#include <cstdint>
#include <math_constants.h>

#define E_DIM 128
#define THREADS 256
#define RB 16                      // rows per block (pass1)
#define VSPLIT 4                   // column chunks
#define VPAD_MAX 50432
#define BMAX 1024
#define NEG_BIG (-3.4e38f)

// Scratch (static device globals: allocation-free per harness rules)
__device__ __align__(16) float g_W[(size_t)E_DIM * VPAD_MAX];  // repacked embed2vocab
__device__ __align__(16) float g_emb[(size_t)BMAX * E_DIM];    // xsembeds
__device__ float2 g_stats[(size_t)BMAX * VSPLIT];              // partial (max, sumexp)
__device__ float  g_lse[BMAX];

// ---------------- packed f32x2 helpers (PTX-only on sm_103a) ----------------
__device__ __forceinline__ void fma2(unsigned long long& d, unsigned long long a, unsigned long long b){
  asm("fma.rn.f32x2 %0, %1, %2, %0;" : "+l"(d) : "l"(a), "l"(b));
}
__device__ __forceinline__ void unpack2(float& lo, float& hi, unsigned long long v){
  asm("mov.b64 {%0, %1}, %2;" : "=f"(lo), "=f"(hi) : "l"(v));
}

// ---------------- K0: repack embed2vocab [E,V] into padded g_W [E,vpad] ----------------
__global__ void repack_kernel(const float* __restrict__ W, int V, int vpad){
  const int e = blockIdx.x;
  const float* src = W + (size_t)e * V;
  float* dst = g_W + (size_t)e * vpad;
  for (int v = threadIdx.x + blockIdx.y * blockDim.x; v < vpad; v += blockDim.x * gridDim.y)
    dst[v] = (v < V) ? src[v] : 0.f;
}

// ---------------- K1: sparse scan + gather: xsembeds = xs @ EMBEDM ----------------
__global__ void gather_kernel(const float* __restrict__ xs, const float* __restrict__ EM, int V){
  __shared__ int   s_cnt;
  __shared__ int   s_v[1024];
  __shared__ float s_w[1024];
  const int b = blockIdx.x;
  const int tid = threadIdx.x;
  if (tid == 0) s_cnt = 0;
  __syncthreads();

  const float* row = xs + (size_t)b * V;
  int a0 = (int)(((16u - ((unsigned)(uintptr_t)row & 15u)) & 15u) >> 2);
  if (a0 > V) a0 = V;
  const int n4 = (V - a0) >> 2;
  const float4* row4 = (const float4*)(row + a0);

  for (int j = tid; j < n4; j += THREADS){
    float4 x = row4[j];
    const int base = a0 + 4*j;
    if (x.x != 0.f){ int p = atomicAdd(&s_cnt,1); if (p<1024){ s_v[p]=base;   s_w[p]=x.x; } }
    if (x.y != 0.f){ int p = atomicAdd(&s_cnt,1); if (p<1024){ s_v[p]=base+1; s_w[p]=x.y; } }
    if (x.z != 0.f){ int p = atomicAdd(&s_cnt,1); if (p<1024){ s_v[p]=base+2; s_w[p]=x.z; } }
    if (x.w != 0.f){ int p = atomicAdd(&s_cnt,1); if (p<1024){ s_v[p]=base+3; s_w[p]=x.w; } }
  }
  for (int i = tid; i < a0; i += THREADS){
    float x = row[i];
    if (x != 0.f){ int p = atomicAdd(&s_cnt,1); if (p<1024){ s_v[p]=i; s_w[p]=x; } }
  }
  for (int i = a0 + 4*n4 + tid; i < V; i += THREADS){
    float x = row[i];
    if (x != 0.f){ int p = atomicAdd(&s_cnt,1); if (p<1024){ s_v[p]=i; s_w[p]=x; } }
  }
  __syncthreads();

  int cnt = s_cnt; if (cnt > 1024) cnt = 1024;
  if (tid < E_DIM){
    float acc = 0.f;
    for (int k = 0; k < cnt; k++)
      acc = fmaf(s_w[k], EM[(size_t)s_v[k]*E_DIM + tid], acc);
    g_emb[(size_t)b*E_DIM + tid] = acc;
  }
}

// ---------------- K2: pass1 — logits + partial (max, sumexp) per (rowblock, chunk) ----------------
// Block = 16 rows x ~V/4 cols. W streamed from L2 (1.65GB total), x broadcast from smem
// as prepacked (x,x) pairs, f32x2 FMAs. Per-thread stats live in smem (reg relief).
// Vq is rounded to a multiple of 4 so every chunk start (and thus every W pointer)
// is 16B-aligned — the R3 crash was chunk1 starting at c0=12565.
__global__ void __launch_bounds__(THREADS, 2)
gemm_pass1_kernel(float* __restrict__ out, int V, int vpad){
  __shared__ __align__(16) unsigned long long s_x2[RB][E_DIM];  // 16KB
  __shared__ float s_rm[RB][THREADS];                            // 16KB
  __shared__ float s_rs[RB][THREADS];                            // 16KB

  const int tid = threadIdx.x;
  const int r0  = blockIdx.x * RB;
  const int q   = blockIdx.y;
  const int Vq  = (((V + VSPLIT - 1) / VSPLIT) + 3) & ~3;  // multiple of 4
  const int c0  = q * Vq;                                   // => c0 % 4 == 0
  const int cend = min(V, c0 + Vq);

  // prepack (x,x) pairs
  for (int i = tid; i < RB*E_DIM; i += THREADS){
    const int r = i >> 7, e = i & (E_DIM-1);
    const float x = g_emb[(size_t)(r0 + r)*E_DIM + e];
    unsigned long long p; asm("mov.b64 %0, {%1, %1};" : "=l"(p) : "f"(x));
    s_x2[r][e] = p;
  }
#pragma unroll
  for (int r = 0; r < RB; r++){ s_rm[r][tid] = NEG_BIG; s_rs[r][tid] = 0.f; }
  __syncthreads();

  for (int cb = c0; cb < cend; cb += THREADS*4){
    const int c = cb + 4*tid;             // multiple of 4 -> 16B-aligned W loads
    unsigned long long acc[RB][2];
#pragma unroll
    for (int r = 0; r < RB; r++){ acc[r][0] = 0ull; acc[r][1] = 0ull; }

    const float* Wc = g_W + c;
#pragma unroll 2
    for (int e2 = 0; e2 < E_DIM/2; e2++){
      const ulonglong2 w0 = *(const ulonglong2*)(Wc + (size_t)(2*e2  )*vpad);
      const ulonglong2 w1 = *(const ulonglong2*)(Wc + (size_t)(2*e2+1)*vpad);
#pragma unroll
      for (int r = 0; r < RB; r++){
        const ulonglong2 xp = *(const ulonglong2*)&s_x2[r][2*e2];  // LDS.128 broadcast
        fma2(acc[r][0], xp.x, w0.x);
        fma2(acc[r][1], xp.x, w0.y);
        fma2(acc[r][0], xp.y, w1.x);
        fma2(acc[r][1], xp.y, w1.y);
      }
    }

    // epilogue: per-col validity guards (vector loads above may cover padding)
    const bool ok0 = (c   < cend), ok1 = (c+1 < cend),
               ok2 = (c+2 < cend), ok3 = (c+3 < cend);
#pragma unroll
    for (int r = 0; r < RB; r++){
      float v0,v1,v2,v3;
      unpack2(v0,v1,acc[r][0]); unpack2(v2,v3,acc[r][1]);
      float mi = NEG_BIG;
      if (ok0) mi = fmaxf(mi, v0);
      if (ok1) mi = fmaxf(mi, v1);
      if (ok2) mi = fmaxf(mi, v2);
      if (ok3) mi = fmaxf(mi, v3);
      float si = 0.f;
      if (ok0) si += __expf(v0 - mi);
      if (ok1) si += __expf(v1 - mi);
      if (ok2) si += __expf(v2 - mi);
      if (ok3) si += __expf(v3 - mi);
      const float m0 = s_rm[r][tid], ss = s_rs[r][tid];
      const float mm = fmaxf(m0, mi);
      s_rs[r][tid] = ss*__expf(m0 - mm) + si*__expf(mi - mm);
      s_rm[r][tid] = mm;
      float* orow = out + (size_t)(r0 + r)*V + c;
      if (ok0) orow[0] = v0;
      if (ok1) orow[1] = v1;
      if (ok2) orow[2] = v2;
      if (ok3) orow[3] = v3;
    }
  }
  __syncthreads();

  // block reduce (max, sumexp) per row
  for (int st = THREADS/2; st > 0; st >>= 1){
    if (tid < st){
#pragma unroll
      for (int r = 0; r < RB; r++){
        const float m1 = s_rm[r][tid],    s1 = s_rs[r][tid];
        const float m2 = s_rm[r][tid+st], s2 = s_rs[r][tid+st];
        const float mm = fmaxf(m1, m2);
        s_rm[r][tid] = mm;
        s_rs[r][tid] = s1*__expf(m1-mm) + s2*__expf(m2-mm);
      }
    }
    __syncthreads();
  }
  if (tid < RB)
    g_stats[(size_t)(r0 + tid)*VSPLIT + q] = make_float2(s_rm[tid][0], s_rs[tid][0]);
}

// ---------------- K3: combine chunk stats -> lse per row ----------------
__global__ void lse_kernel(int B){
  const int row = blockIdx.x * blockDim.x + threadIdx.x;
  if (row < B){
    float m = NEG_BIG, s = 0.f;
#pragma unroll
    for (int q = 0; q < VSPLIT; q++){
      const float2 t = g_stats[(size_t)row*VSPLIT + q];
      const float mm = fmaxf(m, t.x);
      s = s*__expf(m - mm) + t.y*__expf(t.x - mm);
      m = mm;
    }
    g_lse[row] = m + logf(s);
  }
}

// ---------------- K4: subtract lse in-place (row-aligned float4 body) ----------------
__global__ void sub_kernel(float* __restrict__ out, int V){
  const int row = blockIdx.x;
  const float lse = g_lse[row];
  float* p = out + (size_t)row * V;
  int a0 = (int)(((16u - ((unsigned)(uintptr_t)p & 15u)) & 15u) >> 2);
  if (a0 > V) a0 = V;
  for (int i = threadIdx.x; i < a0; i += blockDim.x) p[i] -= lse;
  const int n4 = (V - a0) >> 2;
  float4* p4 = (float4*)(p + a0);
  for (int j = threadIdx.x; j < n4; j += blockDim.x){
    float4 x = p4[j];
    x.x -= lse; x.y -= lse; x.z -= lse; x.w -= lse;
    p4[j] = x;
  }
  for (int i = a0 + 4*n4 + threadIdx.x; i < V; i += blockDim.x) p[i] -= lse;
}

extern "C" void kernel_launch(void* const* d_in, const int* in_sizes, int n_in,
                              void* d_out, int out_size){
  const float* xs = (const float*)d_in[0];
  // d_in[1] = metric (unused by forward)
  const float* EM = (const float*)d_in[2];
  const float* W  = (const float*)d_in[3];
  float* out = (float*)d_out;

  const int V = in_sizes[3] / E_DIM;   // 50257
  const int B = in_sizes[0] / V;       // 1024
  int vpad = (V + 31) & ~31;
  if (vpad > VPAD_MAX) vpad = VPAD_MAX;

  dim3 rg(E_DIM, 8);
  repack_kernel<<<rg, 256>>>(W, V, vpad);
  gather_kernel<<<B, THREADS>>>(xs, EM, V);
  dim3 g1(B / RB, VSPLIT);
  gemm_pass1_kernel<<<g1, THREADS>>>(out, V, vpad);
  lse_kernel<<<(B + 255)/256, 256>>>(B);
  sub_kernel<<<B, 256>>>(out, V);
}

// round 6
// speedup vs baseline: 3.5611x; 1.8286x over previous
#include <cuda_runtime.h>
#include <cuda_bf16.h>
#include <cstdint>

#define E_DIM 128
#define MT 128
#define NTL 128
#define BMAX 1024
#define NTST 400
#define NEG_BIG (-3.0e38f)
#define VPW 50432

// ---- static device scratch (allocation-free) ----
__device__ __align__(16) __nv_bfloat16 g_Whi[(size_t)VPW * E_DIM];
__device__ __align__(16) __nv_bfloat16 g_Wlo[(size_t)VPW * E_DIM];
__device__ __align__(16) __nv_bfloat16 g_Ahi[(size_t)BMAX * E_DIM];
__device__ __align__(16) __nv_bfloat16 g_Alo[(size_t)BMAX * E_DIM];
__device__ float2 g_stats[(size_t)BMAX * NTST];
__device__ float  g_lse[BMAX];

__device__ __forceinline__ uint32_t smem_u32(const void* p){
  uint32_t a; asm("{ .reg .u64 t; cvta.to.shared.u64 t, %1; cvt.u32.u64 %0, t; }" : "=r"(a) : "l"(p));
  return a;
}
__device__ __forceinline__ void split_bf16(float x, __nv_bfloat16& h, __nv_bfloat16& l){
  h = __float2bfloat16(x);
  l = __float2bfloat16(x - __bfloat162float(h));
}
// swizzled byte offset within a 128x128 bf16 tile (rows=256B, 16B chunks)
__device__ __forceinline__ uint32_t swoff(int r, int c){
  return (uint32_t)r*256u + (uint32_t)((c ^ (r & 7)) << 4);
}
// ldmatrix x4: A-fragment order (r0-7,k0-7),(r8-15,k0-7),(r0-7,k8-15),(r8-15,k8-15)
__device__ __forceinline__ void ldmA(uint32_t* f, uint32_t base, int r0, int c0, int lid){
  const uint32_t a = (lid < 16) ? base + swoff(r0 + lid, c0)
                                : base + swoff(r0 + lid - 16, c0 + 1);
  asm volatile("ldmatrix.sync.aligned.m8n8.x4.shared.b16 {%0,%1,%2,%3}, [%4];"
    : "=r"(f[0]), "=r"(f[1]), "=r"(f[2]), "=r"(f[3]) : "r"(a));
}
// ldmatrix x4 for two B n8-frags: (n0-7){b0,b1},(n8-15){b0,b1}
__device__ __forceinline__ void ldmB(uint32_t* f, uint32_t base, int n0, int c0, int lid){
  const int g = lid >> 3, lr = lid & 7;
  const uint32_t a = base + swoff(n0 + lr + ((g & 2) ? 8 : 0), c0 + (g & 1));
  asm volatile("ldmatrix.sync.aligned.m8n8.x4.shared.b16 {%0,%1,%2,%3}, [%4];"
    : "=r"(f[0]), "=r"(f[1]), "=r"(f[2]), "=r"(f[3]) : "r"(a));
}
__device__ __forceinline__ void mma_bf16(float* d, const uint32_t* a, const uint32_t* b){
  asm volatile("mma.sync.aligned.m16n8k16.row.col.f32.bf16.bf16.f32 "
    "{%0,%1,%2,%3}, {%4,%5,%6,%7}, {%8,%9}, {%0,%1,%2,%3};"
    : "+f"(d[0]), "+f"(d[1]), "+f"(d[2]), "+f"(d[3])
    : "r"(a[0]), "r"(a[1]), "r"(a[2]), "r"(a[3]), "r"(b[0]), "r"(b[1]));
}
__device__ __forceinline__ void merge(float& m, float& s, float m2, float s2){
  const float nm = fmaxf(m, m2);
  s = s*__expf(m - nm) + s2*__expf(m2 - nm);
  m = nm;
}

// ---------------- K0: transpose+split W [E,V] -> g_W{hi,lo} [VPW,E] ----------------
__global__ void wsplit_kernel(const float* __restrict__ W, int V){
  __shared__ float t[32][33];
  const int v0 = blockIdx.x*32, e0 = blockIdx.y*32;
  const int tx = threadIdx.x, ty = threadIdx.y;
#pragma unroll
  for (int k = 0; k < 4; k++){
    const int e = e0 + ty*4 + k, v = v0 + tx;
    t[ty*4+k][tx] = (v < V) ? W[(size_t)e*V + v] : 0.f;
  }
  __syncthreads();
#pragma unroll
  for (int k = 0; k < 4; k++){
    const int a = ty*4 + k;
    const float x = t[tx][a];
    __nv_bfloat16 h, l; split_bf16(x, h, l);
    const size_t o = (size_t)(v0 + a)*E_DIM + e0 + tx;
    g_Whi[o] = h; g_Wlo[o] = l;
  }
}

// ---------------- K1: sparse scan + gather -> A hi/lo bf16 ----------------
__global__ void gather_kernel(const float* __restrict__ xs, const float* __restrict__ EM, int V){
  __shared__ int   s_cnt;
  __shared__ int   s_v[1024];
  __shared__ float s_w[1024];
  const int b = blockIdx.x, tid = threadIdx.x;
  if (tid == 0) s_cnt = 0;
  __syncthreads();

  const float* row = xs + (size_t)b * V;
  int a0 = (int)(((16u - ((unsigned)(uintptr_t)row & 15u)) & 15u) >> 2);
  if (a0 > V) a0 = V;
  const int n4 = (V - a0) >> 2;
  const float4* row4 = (const float4*)(row + a0);

  for (int j = tid; j < n4; j += 256){
    float4 x = row4[j];
    const int base = a0 + 4*j;
    if (x.x != 0.f){ int p = atomicAdd(&s_cnt,1); if (p<1024){ s_v[p]=base;   s_w[p]=x.x; } }
    if (x.y != 0.f){ int p = atomicAdd(&s_cnt,1); if (p<1024){ s_v[p]=base+1; s_w[p]=x.y; } }
    if (x.z != 0.f){ int p = atomicAdd(&s_cnt,1); if (p<1024){ s_v[p]=base+2; s_w[p]=x.z; } }
    if (x.w != 0.f){ int p = atomicAdd(&s_cnt,1); if (p<1024){ s_v[p]=base+3; s_w[p]=x.w; } }
  }
  for (int i = tid; i < a0; i += 256){
    float x = row[i];
    if (x != 0.f){ int p = atomicAdd(&s_cnt,1); if (p<1024){ s_v[p]=i; s_w[p]=x; } }
  }
  for (int i = a0 + 4*n4 + tid; i < V; i += 256){
    float x = row[i];
    if (x != 0.f){ int p = atomicAdd(&s_cnt,1); if (p<1024){ s_v[p]=i; s_w[p]=x; } }
  }
  __syncthreads();

  int cnt = s_cnt; if (cnt > 1024) cnt = 1024;
  if (tid < E_DIM){
    float acc = 0.f;
    for (int k = 0; k < cnt; k++)
      acc = fmaf(s_w[k], EM[(size_t)s_v[k]*E_DIM + tid], acc);
    __nv_bfloat16 h, l; split_bf16(acc, h, l);
    g_Ahi[(size_t)b*E_DIM + tid] = h;
    g_Alo[(size_t)b*E_DIM + tid] = l;
  }
}

// ---------------- K2: mma.sync bf16-split GEMM + logits + partial stats ----------------
#define SM_AHI 0
#define SM_ALO 32768
#define SM_WHI 65536
#define SM_WLO 98304
#define SM_STM 131072                       // float[128][4]
#define SM_STS (131072 + 2048)
#define SMEM_GEMM (131072 + 4096)

__global__ void __launch_bounds__(512, 1)
gemm_mma_kernel(float* __restrict__ out, int V){
  extern __shared__ char smem[];
  const uint32_t sb = smem_u32(smem);
  const int tid = threadIdx.x, wid = tid >> 5, lid = tid & 31;
  const int wm = wid >> 2, wn = wid & 3;
  const int ntile = blockIdx.x, mtile = blockIdx.y;
  const int n0 = ntile * NTL, m0 = mtile * MT;

  // tile loads (each tile: 128 rows x 16 uint4), swizzled stores
  for (int idx = tid; idx < 2048; idx += 512){
    const int r = idx >> 4, c = idx & 15;
    const uint32_t off = swoff(r, c);
    *(uint4*)(smem + SM_AHI + off) = ((const uint4*)g_Ahi)[(size_t)(m0 + r)*16 + c];
    *(uint4*)(smem + SM_ALO + off) = ((const uint4*)g_Alo)[(size_t)(m0 + r)*16 + c];
    *(uint4*)(smem + SM_WHI + off) = ((const uint4*)g_Whi)[(size_t)(n0 + r)*16 + c];
    *(uint4*)(smem + SM_WLO + off) = ((const uint4*)g_Wlo)[(size_t)(n0 + r)*16 + c];
  }
  __syncthreads();

  float d[2][4][4];
#pragma unroll
  for (int mf = 0; mf < 2; mf++)
#pragma unroll
    for (int nf = 0; nf < 4; nf++)
#pragma unroll
      for (int k = 0; k < 4; k++) d[mf][nf][k] = 0.f;

  const uint32_t aHi = sb + SM_AHI, aLo = sb + SM_ALO;
  const uint32_t wHi = sb + SM_WHI, wLo = sb + SM_WLO;
  const int rA = 32*wm, rB = 32*wn;

#pragma unroll 4
  for (int s = 0; s < 8; s++){
    const int c0 = 2*s;
    uint32_t ah[2][4], al[2][4], wh[4][2], wl[4][2], t[4];
    ldmA(ah[0], aHi, rA,      c0, lid);
    ldmA(ah[1], aHi, rA + 16, c0, lid);
    ldmA(al[0], aLo, rA,      c0, lid);
    ldmA(al[1], aLo, rA + 16, c0, lid);
    ldmB(t, wHi, rB,      c0, lid); wh[0][0]=t[0]; wh[0][1]=t[1]; wh[1][0]=t[2]; wh[1][1]=t[3];
    ldmB(t, wHi, rB + 16, c0, lid); wh[2][0]=t[0]; wh[2][1]=t[1]; wh[3][0]=t[2]; wh[3][1]=t[3];
    ldmB(t, wLo, rB,      c0, lid); wl[0][0]=t[0]; wl[0][1]=t[1]; wl[1][0]=t[2]; wl[1][1]=t[3];
    ldmB(t, wLo, rB + 16, c0, lid); wl[2][0]=t[0]; wl[2][1]=t[1]; wl[3][0]=t[2]; wl[3][1]=t[3];
#pragma unroll
    for (int mf = 0; mf < 2; mf++)
#pragma unroll
      for (int nf = 0; nf < 4; nf++){
        mma_bf16(d[mf][nf], ah[mf], wh[nf]);   // hi*hi
        mma_bf16(d[mf][nf], ah[mf], wl[nf]);   // hi*lo
        mma_bf16(d[mf][nf], al[mf], wh[nf]);   // lo*hi
      }
  }

  // ---- epilogue: store logits (scalar: V odd kills vector alignment) + stats ----
  float* smM = (float*)(smem + SM_STM);
  float* smS = (float*)(smem + SM_STS);
  const int cq = (lid & 3) * 2;
  const int rq = lid >> 2;

#pragma unroll
  for (int mf = 0; mf < 2; mf++){
    const int row0 = m0 + 32*wm + 16*mf + rq;     // global rows row0, row0+8
    float mx0 = NEG_BIG, mx1 = NEG_BIG;
#pragma unroll
    for (int nf = 0; nf < 4; nf++){
      const int g = n0 + 32*wn + 8*nf + cq;
      // store valid logits first
      if (g < V){
        out[(size_t)row0*V + g]     = d[mf][nf][0];
        out[(size_t)(row0+8)*V + g] = d[mf][nf][2];
      }
      if (g+1 < V){
        out[(size_t)row0*V + g + 1]     = d[mf][nf][1];
        out[(size_t)(row0+8)*V + g + 1] = d[mf][nf][3];
      }
      // mask invalid for stats
      if (g   >= V){ d[mf][nf][0] = NEG_BIG; d[mf][nf][2] = NEG_BIG; }
      if (g+1 >= V){ d[mf][nf][1] = NEG_BIG; d[mf][nf][3] = NEG_BIG; }
      mx0 = fmaxf(mx0, fmaxf(d[mf][nf][0], d[mf][nf][1]));
      mx1 = fmaxf(mx1, fmaxf(d[mf][nf][2], d[mf][nf][3]));
    }
    float s0 = 0.f, s1 = 0.f;
#pragma unroll
    for (int nf = 0; nf < 4; nf++){
      s0 += __expf(d[mf][nf][0]-mx0) + __expf(d[mf][nf][1]-mx0);
      s1 += __expf(d[mf][nf][2]-mx1) + __expf(d[mf][nf][3]-mx1);
    }
    if (mx0 == NEG_BIG) s0 = 0.f;   // fully-invalid lane group
    if (mx1 == NEG_BIG) s1 = 0.f;
    // reduce across the 4 lanes sharing each row
#pragma unroll
    for (int o = 1; o <= 2; o <<= 1){
      merge(mx0, s0, __shfl_xor_sync(0xFFFFFFFFu, mx0, o), __shfl_xor_sync(0xFFFFFFFFu, s0, o));
      merge(mx1, s1, __shfl_xor_sync(0xFFFFFFFFu, mx1, o), __shfl_xor_sync(0xFFFFFFFFu, s1, o));
    }
    if ((lid & 3) == 0){
      const int rl = 32*wm + 16*mf + rq;
      smM[rl*4 + wn] = mx0;        smS[rl*4 + wn] = s0;
      smM[(rl+8)*4 + wn] = mx1;    smS[(rl+8)*4 + wn] = s1;
    }
  }
  __syncthreads();

  if (tid < 128){
    float m = NEG_BIG, s = 0.f;
#pragma unroll
    for (int k = 0; k < 4; k++) merge(m, s, smM[tid*4 + k], smS[tid*4 + k]);
    g_stats[(size_t)(m0 + tid)*NTST + ntile] = make_float2(m, s);
  }
}

// ---------------- K3: combine stats -> lse (one warp per row) ----------------
__global__ void lse_kernel(int B, int NT){
  const int w = (blockIdx.x * blockDim.x + threadIdx.x) >> 5;
  const int lid = threadIdx.x & 31;
  if (w >= B) return;
  float m = NEG_BIG, s = 0.f;
  for (int q = lid; q < NT; q += 32){
    const float2 t = g_stats[(size_t)w*NTST + q];
    merge(m, s, t.x, t.y);
  }
#pragma unroll
  for (int o = 16; o; o >>= 1)
    merge(m, s, __shfl_xor_sync(0xFFFFFFFFu, m, o), __shfl_xor_sync(0xFFFFFFFFu, s, o));
  if (lid == 0) g_lse[w] = m + logf(s);
}

// ---------------- K4: subtract lse in-place ----------------
__global__ void sub_kernel(float* __restrict__ out, int V){
  const int row = blockIdx.x;
  const float lse = g_lse[row];
  float* p = out + (size_t)row * V;
  int a0 = (int)(((16u - ((unsigned)(uintptr_t)p & 15u)) & 15u) >> 2);
  if (a0 > V) a0 = V;
  for (int i = threadIdx.x; i < a0; i += blockDim.x) p[i] -= lse;
  const int n4 = (V - a0) >> 2;
  float4* p4 = (float4*)(p + a0);
  for (int j = threadIdx.x; j < n4; j += blockDim.x){
    float4 x = p4[j];
    x.x -= lse; x.y -= lse; x.z -= lse; x.w -= lse;
    p4[j] = x;
  }
  for (int i = a0 + 4*n4 + threadIdx.x; i < V; i += blockDim.x) p[i] -= lse;
}

extern "C" void kernel_launch(void* const* d_in, const int* in_sizes, int n_in,
                              void* d_out, int out_size){
  const float* xs = (const float*)d_in[0];
  const float* EM = (const float*)d_in[2];
  const float* W  = (const float*)d_in[3];
  float* out = (float*)d_out;

  const int V  = in_sizes[3] / E_DIM;          // 50257
  const int B  = in_sizes[0] / V;              // 1024
  const int NT = (V + NTL - 1) / NTL;          // 393

  cudaFuncSetAttribute(gemm_mma_kernel, cudaFuncAttributeMaxDynamicSharedMemorySize, SMEM_GEMM);

  wsplit_kernel<<<dim3(VPW/32, E_DIM/32), dim3(32, 8)>>>(W, V);
  gather_kernel<<<B, 256>>>(xs, EM, V);
  gemm_mma_kernel<<<dim3(NT, B/MT), 512, SMEM_GEMM>>>(out, V);
  lse_kernel<<<(B*32 + 255)/256, 256>>>(B, NT);
  sub_kernel<<<B, 256>>>(out, V);
}

// round 7
// speedup vs baseline: 3.8316x; 1.0760x over previous
#include <cuda_runtime.h>
#include <cuda_bf16.h>
#include <cstdint>

#define E_DIM 128
#define MT 128
#define NTL 256
#define BMAX 1024
#define NTST 256
#define NEG_BIG (-3.0e38f)
#define VPW 50432

// ---- static device scratch (allocation-free) ----
__device__ __align__(16) __nv_bfloat16 g_Whi[(size_t)VPW * E_DIM];
__device__ __align__(16) __nv_bfloat16 g_Wlo[(size_t)VPW * E_DIM];
__device__ __align__(16) __nv_bfloat16 g_Ahi[(size_t)BMAX * E_DIM];
__device__ __align__(16) __nv_bfloat16 g_Alo[(size_t)BMAX * E_DIM];
__device__ float2 g_stats[(size_t)BMAX * NTST];
__device__ float  g_lse[BMAX];

__device__ __forceinline__ uint32_t smem_u32(const void* p){
  uint32_t a; asm("{ .reg .u64 t; cvta.to.shared.u64 t, %1; cvt.u32.u64 %0, t; }" : "=r"(a) : "l"(p));
  return a;
}
__device__ __forceinline__ void split_bf16(float x, __nv_bfloat16& h, __nv_bfloat16& l){
  h = __float2bfloat16(x);
  l = __float2bfloat16(x - __bfloat162float(h));
}
// swizzled byte offset within a [rows x 128] bf16 tile (256B rows, 16B chunks)
__device__ __forceinline__ uint32_t swoff(int r, int c){
  return (uint32_t)r*256u + (uint32_t)((c ^ (r & 7)) << 4);
}
__device__ __forceinline__ void cp16(uint32_t dst, const void* src){
  asm volatile("cp.async.cg.shared.global [%0], [%1], 16;" :: "r"(dst), "l"(src) : "memory");
}
#define CP_COMMIT() asm volatile("cp.async.commit_group;" ::: "memory")
#define CP_WAIT0()  asm volatile("cp.async.wait_group 0;" ::: "memory")

__device__ __forceinline__ void ldmA(uint32_t* f, uint32_t base, int r0, int c0, int lid){
  const uint32_t a = (lid < 16) ? base + swoff(r0 + lid, c0)
                                : base + swoff(r0 + lid - 16, c0 + 1);
  asm volatile("ldmatrix.sync.aligned.m8n8.x4.shared.b16 {%0,%1,%2,%3}, [%4];"
    : "=r"(f[0]), "=r"(f[1]), "=r"(f[2]), "=r"(f[3]) : "r"(a));
}
__device__ __forceinline__ void ldmB(uint32_t* f, uint32_t base, int n0, int c0, int lid){
  const int g = lid >> 3, lr = lid & 7;
  const uint32_t a = base + swoff(n0 + lr + ((g & 2) ? 8 : 0), c0 + (g & 1));
  asm volatile("ldmatrix.sync.aligned.m8n8.x4.shared.b16 {%0,%1,%2,%3}, [%4];"
    : "=r"(f[0]), "=r"(f[1]), "=r"(f[2]), "=r"(f[3]) : "r"(a));
}
__device__ __forceinline__ void mma_bf16(float* d, const uint32_t* a, const uint32_t* b){
  asm volatile("mma.sync.aligned.m16n8k16.row.col.f32.bf16.bf16.f32 "
    "{%0,%1,%2,%3}, {%4,%5,%6,%7}, {%8,%9}, {%0,%1,%2,%3};"
    : "+f"(d[0]), "+f"(d[1]), "+f"(d[2]), "+f"(d[3])
    : "r"(a[0]), "r"(a[1]), "r"(a[2]), "r"(a[3]), "r"(b[0]), "r"(b[1]));
}
__device__ __forceinline__ void merge(float& m, float& s, float m2, float s2){
  const float nm = fmaxf(m, m2);
  s = s*__expf(m - nm) + s2*__expf(m2 - nm);
  m = nm;
}

// ---------------- K0: fused prep: wsplit blocks + gather blocks ----------------
__global__ void prep_kernel(const float* __restrict__ W, const float* __restrict__ xs,
                            const float* __restrict__ EM, int V, int NWBLK){
  __shared__ float t[32][33];
  __shared__ int   s_cnt;
  __shared__ int   s_v[1024];
  __shared__ float s_w[1024];
  const int tid = threadIdx.x;

  if ((int)blockIdx.x < NWBLK){
    // ---- wsplit: transpose+split W [E,V] -> g_W{hi,lo} [VPW,E] ----
    const int v0 = (blockIdx.x >> 2) * 32, e0 = (blockIdx.x & 3) * 32;
    const int tx = tid & 31, ty = tid >> 5;
#pragma unroll
    for (int k = 0; k < 4; k++){
      const int e = e0 + ty*4 + k, v = v0 + tx;
      t[ty*4+k][tx] = (v < V) ? W[(size_t)e*V + v] : 0.f;
    }
    __syncthreads();
#pragma unroll
    for (int k = 0; k < 4; k++){
      const int a = ty*4 + k;
      const float x = t[tx][a];
      __nv_bfloat16 h, l; split_bf16(x, h, l);
      const size_t o = (size_t)(v0 + a)*E_DIM + e0 + tx;
      g_Whi[o] = h; g_Wlo[o] = l;
    }
    return;
  }

  // ---- gather: sparse scan -> A hi/lo ----
  const int b = blockIdx.x - NWBLK;
  if (tid == 0) s_cnt = 0;
  __syncthreads();

  const float* row = xs + (size_t)b * V;
  int a0 = (int)(((16u - ((unsigned)(uintptr_t)row & 15u)) & 15u) >> 2);
  if (a0 > V) a0 = V;
  const int n4 = (V - a0) >> 2;
  const float4* row4 = (const float4*)(row + a0);

  for (int j = tid; j < n4; j += 256){
    float4 x = row4[j];
    const int base = a0 + 4*j;
    if (x.x != 0.f){ int p = atomicAdd(&s_cnt,1); if (p<1024){ s_v[p]=base;   s_w[p]=x.x; } }
    if (x.y != 0.f){ int p = atomicAdd(&s_cnt,1); if (p<1024){ s_v[p]=base+1; s_w[p]=x.y; } }
    if (x.z != 0.f){ int p = atomicAdd(&s_cnt,1); if (p<1024){ s_v[p]=base+2; s_w[p]=x.z; } }
    if (x.w != 0.f){ int p = atomicAdd(&s_cnt,1); if (p<1024){ s_v[p]=base+3; s_w[p]=x.w; } }
  }
  for (int i = tid; i < a0; i += 256){
    float x = row[i];
    if (x != 0.f){ int p = atomicAdd(&s_cnt,1); if (p<1024){ s_v[p]=i; s_w[p]=x; } }
  }
  for (int i = a0 + 4*n4 + tid; i < V; i += 256){
    float x = row[i];
    if (x != 0.f){ int p = atomicAdd(&s_cnt,1); if (p<1024){ s_v[p]=i; s_w[p]=x; } }
  }
  __syncthreads();

  int cnt = s_cnt; if (cnt > 1024) cnt = 1024;
  if (tid < E_DIM){
    float acc = 0.f;
    for (int k = 0; k < cnt; k++)
      acc = fmaf(s_w[k], EM[(size_t)s_v[k]*E_DIM + tid], acc);
    __nv_bfloat16 h, l; split_bf16(acc, h, l);
    g_Ahi[(size_t)b*E_DIM + tid] = h;
    g_Alo[(size_t)b*E_DIM + tid] = l;
  }
}

// ---------------- K1: mma.sync bf16-split GEMM (128x256 tile) + logits + stats ----------------
#define SM_AHI 0
#define SM_ALO 32768
#define SM_WHI 65536                        // 64KB (256 rows)
#define SM_WLO 131072                       // 64KB
#define SM_STM 196608                       // float[128][4]
#define SM_STS (196608 + 2048)
#define SMEM_GEMM (196608 + 4096)

__global__ void __launch_bounds__(512, 1)
gemm_mma_kernel(float* __restrict__ out, int V){
  extern __shared__ char smem[];
  const uint32_t sb = smem_u32(smem);
  const int tid = threadIdx.x, wid = tid >> 5, lid = tid & 31;
  const int wm = wid >> 2, wn = wid & 3;      // 4 x 4 warps: m32 x n64 each
  const int ntile = blockIdx.x, mtile = blockIdx.y;
  const int n0 = ntile * NTL, m0 = mtile * MT;

  // async tile fill: A hi/lo 128x16 uint4 each, W hi/lo 256x16 uint4 each
  for (int idx = tid; idx < 2048; idx += 512){
    const int r = idx >> 4, c = idx & 15;
    const uint32_t off = swoff(r, c);
    cp16(sb + SM_AHI + off, &((const uint4*)g_Ahi)[(size_t)(m0 + r)*16 + c]);
    cp16(sb + SM_ALO + off, &((const uint4*)g_Alo)[(size_t)(m0 + r)*16 + c]);
  }
  for (int idx = tid; idx < 4096; idx += 512){
    const int r = idx >> 4, c = idx & 15;
    const uint32_t off = swoff(r, c);
    cp16(sb + SM_WHI + off, &((const uint4*)g_Whi)[(size_t)(n0 + r)*16 + c]);
    cp16(sb + SM_WLO + off, &((const uint4*)g_Wlo)[(size_t)(n0 + r)*16 + c]);
  }
  CP_COMMIT();
  CP_WAIT0();
  __syncthreads();

  float d[2][8][4];
#pragma unroll
  for (int mf = 0; mf < 2; mf++)
#pragma unroll
    for (int nf = 0; nf < 8; nf++)
#pragma unroll
      for (int k = 0; k < 4; k++) d[mf][nf][k] = 0.f;

  const uint32_t aHi = sb + SM_AHI, aLo = sb + SM_ALO;
  const uint32_t wHi = sb + SM_WHI, wLo = sb + SM_WLO;
  const int rA = 32*wm, rB = 64*wn;

#pragma unroll 2
  for (int s = 0; s < 8; s++){
    const int c0 = 2*s;
    uint32_t ah[2][4], al[2][4];
    ldmA(ah[0], aHi, rA,      c0, lid);
    ldmA(ah[1], aHi, rA + 16, c0, lid);
    ldmA(al[0], aLo, rA,      c0, lid);
    ldmA(al[1], aLo, rA + 16, c0, lid);
#pragma unroll
    for (int h = 0; h < 2; h++){                 // two n32 halves: caps live regs
      uint32_t wh[4][2], wl[4][2], t[4];
      const int nb = rB + 32*h;
      ldmB(t, wHi, nb,      c0, lid); wh[0][0]=t[0]; wh[0][1]=t[1]; wh[1][0]=t[2]; wh[1][1]=t[3];
      ldmB(t, wHi, nb + 16, c0, lid); wh[2][0]=t[0]; wh[2][1]=t[1]; wh[3][0]=t[2]; wh[3][1]=t[3];
      ldmB(t, wLo, nb,      c0, lid); wl[0][0]=t[0]; wl[0][1]=t[1]; wl[1][0]=t[2]; wl[1][1]=t[3];
      ldmB(t, wLo, nb + 16, c0, lid); wl[2][0]=t[0]; wl[2][1]=t[1]; wl[3][0]=t[2]; wl[3][1]=t[3];
#pragma unroll
      for (int mf = 0; mf < 2; mf++)
#pragma unroll
        for (int j = 0; j < 4; j++){
          float* acc = d[mf][4*h + j];
          mma_bf16(acc, ah[mf], wh[j]);   // hi*hi
          mma_bf16(acc, ah[mf], wl[j]);   // hi*lo
          mma_bf16(acc, al[mf], wh[j]);   // lo*hi
        }
    }
  }

  // ---- epilogue: scalar logit stores (V odd) + online stats ----
  float* smM = (float*)(smem + SM_STM);
  float* smS = (float*)(smem + SM_STS);
  const int cq = (lid & 3) * 2;
  const int rq = lid >> 2;

#pragma unroll
  for (int mf = 0; mf < 2; mf++){
    const int row0 = m0 + 32*wm + 16*mf + rq;
    float mx0 = NEG_BIG, mx1 = NEG_BIG;
#pragma unroll
    for (int nf = 0; nf < 8; nf++){
      const int g = n0 + 64*wn + 8*nf + cq;
      if (g < V){
        out[(size_t)row0*V + g]     = d[mf][nf][0];
        out[(size_t)(row0+8)*V + g] = d[mf][nf][2];
      }
      if (g+1 < V){
        out[(size_t)row0*V + g + 1]     = d[mf][nf][1];
        out[(size_t)(row0+8)*V + g + 1] = d[mf][nf][3];
      }
      if (g   >= V){ d[mf][nf][0] = NEG_BIG; d[mf][nf][2] = NEG_BIG; }
      if (g+1 >= V){ d[mf][nf][1] = NEG_BIG; d[mf][nf][3] = NEG_BIG; }
      mx0 = fmaxf(mx0, fmaxf(d[mf][nf][0], d[mf][nf][1]));
      mx1 = fmaxf(mx1, fmaxf(d[mf][nf][2], d[mf][nf][3]));
    }
    float s0 = 0.f, s1 = 0.f;
#pragma unroll
    for (int nf = 0; nf < 8; nf++){
      s0 += __expf(d[mf][nf][0]-mx0) + __expf(d[mf][nf][1]-mx0);
      s1 += __expf(d[mf][nf][2]-mx1) + __expf(d[mf][nf][3]-mx1);
    }
    if (mx0 == NEG_BIG) s0 = 0.f;
    if (mx1 == NEG_BIG) s1 = 0.f;
#pragma unroll
    for (int o = 1; o <= 2; o <<= 1){
      merge(mx0, s0, __shfl_xor_sync(0xFFFFFFFFu, mx0, o), __shfl_xor_sync(0xFFFFFFFFu, s0, o));
      merge(mx1, s1, __shfl_xor_sync(0xFFFFFFFFu, mx1, o), __shfl_xor_sync(0xFFFFFFFFu, s1, o));
    }
    if ((lid & 3) == 0){
      const int rl = 32*wm + 16*mf + rq;
      smM[rl*4 + wn] = mx0;        smS[rl*4 + wn] = s0;
      smM[(rl+8)*4 + wn] = mx1;    smS[(rl+8)*4 + wn] = s1;
    }
  }
  __syncthreads();

  if (tid < 128){
    float m = NEG_BIG, s = 0.f;
#pragma unroll
    for (int k = 0; k < 4; k++) merge(m, s, smM[tid*4 + k], smS[tid*4 + k]);
    g_stats[(size_t)(m0 + tid)*NTST + ntile] = make_float2(m, s);
  }
}

// ---------------- K2: combine stats -> lse (one warp per row) ----------------
__global__ void lse_kernel(int B, int NT){
  const int w = (blockIdx.x * blockDim.x + threadIdx.x) >> 5;
  const int lid = threadIdx.x & 31;
  if (w >= B) return;
  float m = NEG_BIG, s = 0.f;
  for (int q = lid; q < NT; q += 32){
    const float2 t = g_stats[(size_t)w*NTST + q];
    merge(m, s, t.x, t.y);
  }
#pragma unroll
  for (int o = 16; o; o >>= 1)
    merge(m, s, __shfl_xor_sync(0xFFFFFFFFu, m, o), __shfl_xor_sync(0xFFFFFFFFu, s, o));
  if (lid == 0) g_lse[w] = m + logf(s);
}

// ---------------- K3: subtract lse in-place ----------------
__global__ void sub_kernel(float* __restrict__ out, int V){
  const int row = blockIdx.x;
  const float lse = g_lse[row];
  float* p = out + (size_t)row * V;
  int a0 = (int)(((16u - ((unsigned)(uintptr_t)p & 15u)) & 15u) >> 2);
  if (a0 > V) a0 = V;
  for (int i = threadIdx.x; i < a0; i += blockDim.x) p[i] -= lse;
  const int n4 = (V - a0) >> 2;
  float4* p4 = (float4*)(p + a0);
  for (int j = threadIdx.x; j < n4; j += blockDim.x){
    float4 x = p4[j];
    x.x -= lse; x.y -= lse; x.z -= lse; x.w -= lse;
    p4[j] = x;
  }
  for (int i = a0 + 4*n4 + threadIdx.x; i < V; i += blockDim.x) p[i] -= lse;
}

extern "C" void kernel_launch(void* const* d_in, const int* in_sizes, int n_in,
                              void* d_out, int out_size){
  const float* xs = (const float*)d_in[0];
  const float* EM = (const float*)d_in[2];
  const float* W  = (const float*)d_in[3];
  float* out = (float*)d_out;

  const int V  = in_sizes[3] / E_DIM;          // 50257
  const int B  = in_sizes[0] / V;              // 1024
  const int NT = (V + NTL - 1) / NTL;          // 197
  const int NWBLK = (VPW/32) * 4;              // 6304 wsplit blocks

  cudaFuncSetAttribute(gemm_mma_kernel, cudaFuncAttributeMaxDynamicSharedMemorySize, SMEM_GEMM);

  prep_kernel<<<NWBLK + B, 256>>>(W, xs, EM, V, NWBLK);
  gemm_mma_kernel<<<dim3(NT, B/MT), 512, SMEM_GEMM>>>(out, V);
  lse_kernel<<<(B*32 + 255)/256, 256>>>(B, NT);
  sub_kernel<<<B, 256>>>(out, V);
}